// round 17
// baseline (speedup 1.0000x reference)
#include <cuda_runtime.h>
#include <cuda_bf16.h>
#include <math.h>
#include <stdint.h>

#define BB 128
#define TT 512
#define OBS 128
#define ENC 512
#define HHD 512
#define AA 18
#define MM (BB*TT)
#define G4 (4*HHD)

#define N_LOGITS ((size_t)MM*AA)
#define OFF_LOGITS ((size_t)0)
#define OFF_VALUES (N_LOGITS)
#define OFF_HT (OFF_VALUES + (size_t)MM)
#define OFF_CT (OFF_HT + (size_t)BB*HHD)
#define OFF_AR (OFF_CT + (size_t)BB*HHD)
#define OFF_TAR (OFF_AR + 1)
#define NGATE ((size_t)MM*HHD)
#define OFF_IG (OFF_TAR + 1)
#define OFF_FG (OFF_IG + NGATE)
#define OFF_GG (OFF_FG + NGATE)
#define OFF_OG (OFF_GG + NGATE)

__device__ __align__(16) float g_enc1[(size_t)MM*ENC];   // LSTM out (B,T,H)
__device__ __align__(16) float g_xg[(size_t)MM*G4];
// h as pre-split bf16 pairs (hi / lo arrays), double-buffered
__device__ __align__(16) uint32_t g_hhp[2][BB*256];
__device__ __align__(16) uint32_t g_hlp[2][BB*256];
// W_hh in MMA-fragment layout: uint4{b0h,b1h,b0l,b1l} per (n, ki, tig)
__device__ __align__(16) uint4 g_whhF[(size_t)G4*32*4];
// split-bf16 packed activations & weights for feed-forward GEMMs
__device__ __align__(16) uint32_t g_obsp[(size_t)MM*OBS];
__device__ __align__(16) uint32_t g_enc1p[(size_t)MM*ENC];
__device__ __align__(16) uint32_t g_enc2p[(size_t)MM*ENC];
__device__ __align__(16) uint32_t g_w1p[ENC*OBS];
__device__ __align__(16) uint32_t g_w2p[ENC*ENC];
__device__ __align__(16) uint32_t g_wihp[G4*ENC];
#define LOSS_BLOCKS 2048
__device__ double g_part[2][LOSS_BLOCKS];
__device__ unsigned g_arriveG[4];
__device__ unsigned g_releaseG[4];

__device__ __forceinline__ uint32_t packsplit(float x){
    __nv_bfloat16 h = __float2bfloat16(x);
    float r = x - __bfloat162float(h);
    __nv_bfloat16 l = __float2bfloat16(r);
    return (uint32_t)(*(uint16_t*)&h) | ((uint32_t)(*(uint16_t*)&l) << 16);
}
__device__ __forceinline__ void split2(float x0, float x1, uint32_t& hi, uint32_t& lo){
    __nv_bfloat16 h0 = __float2bfloat16(x0), h1 = __float2bfloat16(x1);
    float r0 = x0 - __bfloat162float(h0), r1 = x1 - __bfloat162float(h1);
    __nv_bfloat16 l0 = __float2bfloat16(r0), l1 = __float2bfloat16(r1);
    hi = (uint32_t)(*(uint16_t*)&h0) | ((uint32_t)(*(uint16_t*)&h1) << 16);
    lo = (uint32_t)(*(uint16_t*)&l0) | ((uint32_t)(*(uint16_t*)&l1) << 16);
}
__device__ __forceinline__ void mma16816(float* c, const uint32_t* a, uint32_t b0, uint32_t b1){
    asm volatile("mma.sync.aligned.m16n8k16.row.col.f32.bf16.bf16.f32 "
        "{%0,%1,%2,%3}, {%4,%5,%6,%7}, {%8,%9}, {%0,%1,%2,%3};"
        : "+f"(c[0]), "+f"(c[1]), "+f"(c[2]), "+f"(c[3])
        : "r"(a[0]), "r"(a[1]), "r"(a[2]), "r"(a[3]), "r"(b0), "r"(b1));
}

// ============ pack + init ============
__global__ __launch_bounds__(256)
void conv_init(const float* __restrict__ obs, const float* __restrict__ W1,
               const float* __restrict__ W2, const float* __restrict__ Wih,
               const float* __restrict__ Whh, const float* __restrict__ hxs)
{
    const size_t stride = (size_t)gridDim.x * 256;
    size_t i0 = (size_t)blockIdx.x * 256 + threadIdx.x;
    for (size_t i=i0; i<(size_t)MM*OBS; i+=stride) g_obsp[i] = packsplit(obs[i]);
    for (size_t i=i0; i<(size_t)ENC*OBS; i+=stride) g_w1p[i]  = packsplit(W1[i]);
    for (size_t i=i0; i<(size_t)ENC*ENC; i+=stride) g_w2p[i]  = packsplit(W2[i]);
    for (size_t i=i0; i<(size_t)G4*ENC;  i+=stride) g_wihp[i] = packsplit(Wih[i]);
    // W_hh MMA-fragment layout
    for (size_t idx=i0; idx<(size_t)G4*32*4; idx+=stride){
        int n = (int)(idx >> 7);
        int ki = (int)((idx >> 2) & 31);
        int tig = (int)(idx & 3);
        int k0 = ki*16 + tig*2;
        const float* wr = Whh + (size_t)n*HHD;
        uint32_t b0h, b0l, b1h, b1l;
        split2(wr[k0],   wr[k0+1], b0h, b0l);
        split2(wr[k0+8], wr[k0+9], b1h, b1l);
        g_whhF[idx] = make_uint4(b0h, b1h, b0l, b1l);
    }
    // initial h (hxs) into split pair arrays
    for (size_t idx=i0; idx<(size_t)BB*256; idx+=stride){
        int r = (int)(idx >> 8), p = (int)(idx & 255);
        uint32_t hi, lo;
        split2(hxs[(size_t)r*HHD + 2*p], hxs[(size_t)r*HHD + 2*p + 1], hi, lo);
        g_hhp[0][idx] = hi; g_hlp[0][idx] = lo;
    }
    if (blockIdx.x==0 && threadIdx.x==0){
#pragma unroll
        for (int g=0;g<4;g++){ g_arriveG[g]=0u; g_releaseG[g]=0u; }
    }
}

// ============ HMMA split-bf16 GEMM (NT) ============ (R16, unchanged)
template<int ACT, int OUT_PACK>
__global__ __launch_bounds__(256)
void gemm_mma(const uint32_t* __restrict__ A, const uint32_t* __restrict__ Bw,
              const float* __restrict__ bias1, const float* __restrict__ bias2,
              void* __restrict__ Cout, int K, int N)
{
    __shared__ __align__(16) __nv_bfloat16 sAh[128][40];
    __shared__ __align__(16) __nv_bfloat16 sAl[128][40];
    __shared__ __align__(16) __nv_bfloat16 sBh[128][40];
    __shared__ __align__(16) __nv_bfloat16 sBl[128][40];
    __shared__ float sbias[128];
    const int tid = threadIdx.x;
    const int lane = tid & 31, wid = tid >> 5;
    const int wm = (wid & 3) * 32, wn = (wid >> 2) * 64;
    const size_t m0 = (size_t)blockIdx.y * 128;
    const int n0 = blockIdx.x * 128;
    const int group = lane >> 2, tig = lane & 3;

    if (tid < 128) sbias[tid] = bias1[n0+tid] + (bias2 ? bias2[n0+tid] : 0.f);

    float acc[2][8][4];
#pragma unroll
    for (int i=0;i<2;i++)
#pragma unroll
        for (int j=0;j<8;j++)
#pragma unroll
            for (int q=0;q<4;q++) acc[i][j][q]=0.f;

    for (int kt = 0; kt < K; kt += 32){
        __syncthreads();
        for (int idx = tid; idx < 2048; idx += 256){
            int sel = idx >> 10;
            int l = idx & 1023;
            int row = l >> 3, q = l & 7;
            const uint32_t* src = sel ? (Bw + (size_t)(n0+row)*K + kt + q*4)
                                      : (A + (m0+row)*(size_t)K + kt + q*4);
            uint4 v = __ldcg((const uint4*)src);
            uint32_t h0 = (v.x & 0xffffu) | (v.y << 16);
            uint32_t h1 = (v.z & 0xffffu) | (v.w << 16);
            uint32_t l0 = (v.x >> 16) | (v.y & 0xffff0000u);
            uint32_t l1 = (v.z >> 16) | (v.w & 0xffff0000u);
            uint32_t* dh = (uint32_t*)(sel ? &sBh[row][q*4] : &sAh[row][q*4]);
            uint32_t* dl = (uint32_t*)(sel ? &sBl[row][q*4] : &sAl[row][q*4]);
            dh[0]=h0; dh[1]=h1; dl[0]=l0; dl[1]=l1;
        }
        __syncthreads();
#pragma unroll
        for (int ks = 0; ks < 32; ks += 16){
            uint32_t ah[2][4], al[2][4];
#pragma unroll
            for (int mt=0; mt<2; mt++){
                int m = wm + mt*16 + group;
                int kc = ks + tig*2;
                ah[mt][0] = *(const uint32_t*)&sAh[m][kc];
                ah[mt][1] = *(const uint32_t*)&sAh[m+8][kc];
                ah[mt][2] = *(const uint32_t*)&sAh[m][kc+8];
                ah[mt][3] = *(const uint32_t*)&sAh[m+8][kc+8];
                al[mt][0] = *(const uint32_t*)&sAl[m][kc];
                al[mt][1] = *(const uint32_t*)&sAl[m+8][kc];
                al[mt][2] = *(const uint32_t*)&sAl[m][kc+8];
                al[mt][3] = *(const uint32_t*)&sAl[m+8][kc+8];
            }
#pragma unroll
            for (int nt=0; nt<8; nt++){
                int n = wn + nt*8 + group;
                int kc = ks + tig*2;
                uint32_t bh0 = *(const uint32_t*)&sBh[n][kc];
                uint32_t bh1 = *(const uint32_t*)&sBh[n][kc+8];
                uint32_t bl0 = *(const uint32_t*)&sBl[n][kc];
                uint32_t bl1 = *(const uint32_t*)&sBl[n][kc+8];
#pragma unroll
                for (int mt=0; mt<2; mt++){
                    mma16816(acc[mt][nt], ah[mt], bh0, bh1);
                    mma16816(acc[mt][nt], al[mt], bh0, bh1);
                    mma16816(acc[mt][nt], ah[mt], bl0, bl1);
                }
            }
        }
    }

#pragma unroll
    for (int mt=0; mt<2; mt++){
#pragma unroll
        for (int nt=0; nt<8; nt++){
            int ncol = wn + nt*8 + tig*2;
            float b0 = sbias[ncol], b1 = sbias[ncol+1];
            size_t gm0 = m0 + wm + mt*16 + group;
            size_t gn  = (size_t)n0 + ncol;
            float x0 = acc[mt][nt][0] + b0, x1 = acc[mt][nt][1] + b1;
            float x2 = acc[mt][nt][2] + b0, x3 = acc[mt][nt][3] + b1;
            if (ACT==1){
                x0 = x0/(1.f+expf(-x0)); x1 = x1/(1.f+expf(-x1));
                x2 = x2/(1.f+expf(-x2)); x3 = x3/(1.f+expf(-x3));
            }
            if (OUT_PACK){
                uint32_t* C = (uint32_t*)Cout;
                *(uint2*)(C + gm0*(size_t)N + gn) = make_uint2(packsplit(x0), packsplit(x1));
                *(uint2*)(C + (gm0+8)*(size_t)N + gn) = make_uint2(packsplit(x2), packsplit(x3));
            } else {
                float* C = (float*)Cout;
                *(float2*)(C + gm0*(size_t)N + gn) = make_float2(x0, x1);
                *(float2*)(C + (gm0+8)*(size_t)N + gn) = make_float2(x2, x3);
            }
        }
    }
}

// ================= Persistent LSTM v5: HMMA recurrent GEMM =================
// 128 CTAs = 4 b-groups(32 rows) x 32 h-tiles(16 h). 256 thr = 8 warps =
// (2 M-halves x 4 gates). M32 x N64 x K512 per CTA/step via mma.m16n8k16,
// 3-pass split-bf16. A (h) staged as pre-split hi/lo pair arrays (stride-260
// rows: fragment LDS banks = 4*group+tig, conflict-free). B (W_hh) fragments
// LDG.128 from the precomputed g_whhF layout (128KB/CTA, L1-resident).
// Pre-acts exchanged via pact[cell][4]; activations exact (grouped rcp).
__global__ __launch_bounds__(256, 1)
void lstm_kernel(const uint4* __restrict__ whhF, const float* __restrict__ cxs,
                 float* __restrict__ dout)
{
    extern __shared__ __align__(16) uint32_t smw[];
    uint32_t* sHh = smw;                 // [32][260]
    uint32_t* sHl = sHh + 32*260;        // [32][260]
    float* xsm  = (float*)(sHl + 32*260); // [512][4]
    float* pact = xsm + 2048;             // [512][4]
    const int tid   = threadIdx.x;
    const int grp   = blockIdx.x & 3;
    const int b0    = grp * 32;
    const int hbase = (blockIdx.x >> 2) * 16;
    const int lane  = tid & 31, wid = tid >> 5;
    const int group = lane >> 2, tig = lane & 3;
    const int mh16  = (wid & 1) * 16;
    const int gate  = wid >> 1;
    const int prow  = mh16 + group;

    const uint32_t* hh0 = sHh + prow*260;
    const uint32_t* hh8 = hh0 + 8*260;
    const uint32_t* hl0 = sHl + prow*260;
    const uint32_t* hl8 = hl0 + 8*260;
    const uint4* wf0 = whhF + (size_t)(gate*HHD + hbase + group)*128 + tig;
    const uint4* wf1 = wf0 + (size_t)8*128;

    // phase2 cells: cellA = tid (rows 0..15), cellB = tid+256 (rows 16..31)
    const int rA = tid >> 4, hlA = tid & 15;
    const int rB = rA + 16;
    float cA = cxs[(size_t)(b0+rA)*HHD + hbase + hlA];
    float cB = cxs[(size_t)(b0+rB)*HHD + hbase + hlA];

    float* outb = g_enc1;
    float* gp1 = dout + OFF_IG;  float* gp2 = dout + OFF_FG;
    float* gp3 = dout + OFF_GG;  float* gp4 = dout + OFF_OG;
    unsigned* arr = &g_arriveG[grp];
    unsigned* rel = &g_releaseG[grp];

    for (int t=0;t<TT;t++){
        const uint32_t* hhin = g_hhp[t&1];
        const uint32_t* hlin = g_hlp[t&1];
        uint32_t* hhnx = g_hhp[(t+1)&1];
        uint32_t* hlnx = g_hlp[(t+1)&1];

        // stage h pairs (32 rows x 64 uint4 per array)
#pragma unroll 4
        for (int l=tid;l<2048;l+=256){
            int row = l>>6, q = l&63;
            uint4 vh = __ldcv((const uint4*)(hhin + (size_t)(b0+row)*256) + q);
            uint4 vl = __ldcv((const uint4*)(hlin + (size_t)(b0+row)*256) + q);
            *(uint4*)(sHh + row*260 + q*4) = vh;
            *(uint4*)(sHl + row*260 + q*4) = vl;
        }
        // stage xg into xsm[cell][gate]
#pragma unroll 2
        for (int l=tid;l<512;l+=256){
            int r = l>>4, rem = l&15, g = rem>>2, q = (rem&3)<<2;
            float4 v = __ldcg((const float4*)(g_xg + ((size_t)(b0+r)*TT + t)*G4 + (size_t)g*HHD + hbase + q));
            xsm[(r*16 + q+0)*4 + g] = v.x;
            xsm[(r*16 + q+1)*4 + g] = v.y;
            xsm[(r*16 + q+2)*4 + g] = v.z;
            xsm[(r*16 + q+3)*4 + g] = v.w;
        }
        __syncthreads();

        // ---- MMA mainloop: 32 k-iters, 2 nfrags, 3 passes ----
        float acc0[4] = {0.f,0.f,0.f,0.f};
        float acc1[4] = {0.f,0.f,0.f,0.f};
#pragma unroll 4
        for (int ki=0; ki<32; ki++){
            int pb = ki*8 + tig;
            uint32_t a_h[4] = { hh0[pb], hh8[pb], hh0[pb+4], hh8[pb+4] };
            uint32_t a_l[4] = { hl0[pb], hl8[pb], hl0[pb+4], hl8[pb+4] };
            uint4 w0 = __ldg(wf0 + ki*4);
            uint4 w1 = __ldg(wf1 + ki*4);
            mma16816(acc0, a_h, w0.x, w0.y);
            mma16816(acc0, a_l, w0.x, w0.y);
            mma16816(acc0, a_h, w0.z, w0.w);
            mma16816(acc1, a_h, w1.x, w1.y);
            mma16816(acc1, a_l, w1.x, w1.y);
            mma16816(acc1, a_h, w1.z, w1.w);
        }
        // scatter pre-acts: pact[(row*16 + hl)*4 + gate]
        {
            int hl0c = 0*8 + tig*2;
            pact[((prow   )*16 + hl0c  )*4 + gate] = acc0[0];
            pact[((prow   )*16 + hl0c+1)*4 + gate] = acc0[1];
            pact[((prow+8 )*16 + hl0c  )*4 + gate] = acc0[2];
            pact[((prow+8 )*16 + hl0c+1)*4 + gate] = acc0[3];
            int hl1c = 1*8 + tig*2;
            pact[((prow   )*16 + hl1c  )*4 + gate] = acc1[0];
            pact[((prow   )*16 + hl1c+1)*4 + gate] = acc1[1];
            pact[((prow+8 )*16 + hl1c  )*4 + gate] = acc1[2];
            pact[((prow+8 )*16 + hl1c+1)*4 + gate] = acc1[3];
        }
        __syncthreads();

        // ---- phase 2: activations for 2 cells (exact, grouped rcp) ----
        float hoA, hoB, igA,fgA,ggA,ogA, igB,fgB,ggB,ogB;
#pragma unroll
        for (int cell=0; cell<2; cell++){
            int ci = tid + cell*256;
            float4 pa = *(const float4*)&pact[ci*4];
            float4 xa = *(const float4*)&xsm[ci*4];
            float p0 = pa.x + xa.x, p1 = pa.y + xa.y, p2 = pa.z + xa.z, p3 = pa.w + xa.w;
            float ei = expf(-p0);
            float ef = expf(-p1);
            float eg = expf(-2.f*p2);
            float eo = expf(-p3);
            float d0 = 1.f+ei, d1 = 1.f+ef, d2 = 1.f+eg, d3 = 1.f+eo;
            float p01 = d0*d1, p23 = d2*d3;
            float rp = 1.f/(p01*p23);
            float ig = rp*d1*p23;
            float fg = rp*d0*p23;
            float gg = (1.f-eg)*(rp*p01*d3);
            float og = rp*p01*d2;
            float cc = cell ? cB : cA;
            cc = fg*cc + ig*gg;
            float ec = expf(-2.f*cc);
            float tc = (1.f-ec)/(1.f+ec);
            float ho = og*tc;
            if (cell){ cB=cc; hoB=ho; igB=ig; fgB=fg; ggB=gg; ogB=og; }
            else     { cA=cc; hoA=ho; igA=ig; fgA=fg; ggA=gg; ogA=og; }
            // pack & store split h (pair with hl neighbor via shuffle)
            __nv_bfloat16 bh = __float2bfloat16(ho);
            float rlo = ho - __bfloat162float(bh);
            __nv_bfloat16 bl = __float2bfloat16(rlo);
            uint32_t mine = (uint32_t)(*(uint16_t*)&bh) | ((uint32_t)(*(uint16_t*)&bl) << 16);
            uint32_t oth = __shfl_xor_sync(0xffffffffu, mine, 1);
            if ((tid & 1) == 0){
                int r = cell ? rB : rA;
                size_t pidx = (size_t)(b0+r)*256 + (hbase>>1) + (hlA>>1);
                hhnx[pidx] = (mine & 0xffffu) | (oth << 16);
                hlnx[pidx] = (mine >> 16) | (oth & 0xffff0000u);
            }
        }

        __syncthreads();   // all h stores issued before arrive
        if (tid==0){
            unsigned v;
            asm volatile("atom.release.gpu.global.add.u32 %0, [%1], %2;"
                         : "=r"(v) : "l"(arr), "r"(1u) : "memory");
            if (v == 31u){
                *arr = 0u;
                asm volatile("st.release.gpu.global.u32 [%0], %1;"
                             :: "l"(rel), "r"((unsigned)(t+1)) : "memory");
            }
        }
        // gate/out stores overlap the barrier poll
        {
            size_t baseA = ((size_t)(b0+rA)*TT + t)*HHD + hbase + hlA;
            size_t baseB = ((size_t)(b0+rB)*TT + t)*HHD + hbase + hlA;
            __stcg(outb + baseA, hoA);  __stcg(outb + baseB, hoB);
            __stcg(gp1 + baseA, igA);   __stcg(gp1 + baseB, igB);
            __stcg(gp2 + baseA, fgA);   __stcg(gp2 + baseB, fgB);
            __stcg(gp3 + baseA, ggA);   __stcg(gp3 + baseB, ggB);
            __stcg(gp4 + baseA, ogA);   __stcg(gp4 + baseB, ogB);
        }
        if (t==TT-1){
            dout[OFF_HT + (size_t)(b0+rA)*HHD + hbase + hlA] = hoA;
            dout[OFF_HT + (size_t)(b0+rB)*HHD + hbase + hlA] = hoB;
            dout[OFF_CT + (size_t)(b0+rA)*HHD + hbase + hlA] = cA;
            dout[OFF_CT + (size_t)(b0+rB)*HHD + hbase + hlA] = cB;
        }
        if (tid==0){
            unsigned r;
            do {
                asm volatile("ld.acquire.gpu.global.u32 %0, [%1];"
                             : "=r"(r) : "l"(rel) : "memory");
            } while (r < (unsigned)(t+1));
        }
        __syncthreads();
    }
}

__global__ __launch_bounds__(256)
void head_kernel(const float* __restrict__ Wa, const float* __restrict__ ba,
                 const float* __restrict__ Wc, const float* __restrict__ bc,
                 float* __restrict__ dout)
{
    __shared__ __align__(16) float xsr[16][516];
    const int tid = threadIdx.x;
    const size_t m0 = (size_t)blockIdx.x * 16;
    for (int l=tid;l<2048;l+=256){
        int r=l>>7, c4=(l&127)<<2;
        *(float4*)&xsr[r][c4] = *(const float4*)(g_enc1 + (m0+r)*HHD + c4);
    }
    __syncthreads();
    for (int o=tid;o<16*19;o+=256){
        int r=o/19, n=o-r*19;
        const float* wrow = (n<18) ? (Wa + (size_t)n*HHD) : Wc;
        float acc=0.f;
#pragma unroll 4
        for (int k=0;k<HHD;k+=4){
            float4 w = __ldg((const float4*)(wrow+k));
            float4 x = *(const float4*)&xsr[r][k];
            acc += x.x*w.x + x.y*w.y + x.z*w.z + x.w*w.w;
        }
        size_t m = m0 + r;
        if (n<18) dout[OFF_LOGITS + m*AA + n] = acc + ba[n];
        else      dout[OFF_VALUES + m] = acc + bc[0];
    }
}

__global__ __launch_bounds__(256)
void loss_partial()
{
    float s1=0.f, s2=0.f;
    const size_t n = (size_t)MM*HHD;
    for (size_t i=(size_t)blockIdx.x*256+threadIdx.x; i<n; i+=(size_t)LOSS_BLOCKS*256){
        float x = g_enc1[i];
        s1 += x*x;
        unsigned t = ((unsigned)(i>>9)) & 511u;
        if (t != 511u){ float d = g_enc1[i+512] - x; s2 += d*d; }
    }
    __shared__ double r1[256], r2[256];
    r1[threadIdx.x]=(double)s1; r2[threadIdx.x]=(double)s2;
    __syncthreads();
    for (int s=128;s>0;s>>=1){
        if (threadIdx.x<s){ r1[threadIdx.x]+=r1[threadIdx.x+s]; r2[threadIdx.x]+=r2[threadIdx.x+s]; }
        __syncthreads();
    }
    if (threadIdx.x==0){ g_part[0][blockIdx.x]=r1[0]; g_part[1][blockIdx.x]=r2[0]; }
}

__global__ void loss_final(float* __restrict__ dout)
{
    __shared__ double r1[256], r2[256];
    double s1=0.0, s2=0.0;
    for (int i=threadIdx.x;i<LOSS_BLOCKS;i+=256){ s1+=g_part[0][i]; s2+=g_part[1][i]; }
    r1[threadIdx.x]=s1; r2[threadIdx.x]=s2;
    __syncthreads();
    for (int s=128;s>0;s>>=1){
        if (threadIdx.x<s){ r1[threadIdx.x]+=r1[threadIdx.x+s]; r2[threadIdx.x]+=r2[threadIdx.x+s]; }
        __syncthreads();
    }
    if (threadIdx.x==0){
        dout[OFF_AR]  = (float)(r1[0] * (0.01 / ((double)MM * HHD)));
        dout[OFF_TAR] = (float)(r2[0] * (0.01 / ((double)BB * (TT-1) * HHD)));
    }
}

extern "C" void kernel_launch(void* const* d_in, const int* in_sizes, int n_in,
                              void* d_out, int out_size)
{
    const float* obs  = (const float*)d_in[0];
    const float* hxs  = (const float*)d_in[1];
    const float* cxs  = (const float*)d_in[2];
    const float* W1   = (const float*)d_in[3];
    const float* b1   = (const float*)d_in[4];
    const float* W2   = (const float*)d_in[5];
    const float* b2   = (const float*)d_in[6];
    const float* W_ih = (const float*)d_in[7];
    const float* W_hh = (const float*)d_in[8];
    const float* b_ih = (const float*)d_in[9];
    const float* b_hh = (const float*)d_in[10];
    const float* Wa   = (const float*)d_in[11];
    const float* ba   = (const float*)d_in[12];
    const float* Wc   = (const float*)d_in[13];
    const float* bc   = (const float*)d_in[14];
    float* dout = (float*)d_out;

    uint32_t *obsp, *w1p, *w2p, *wihp, *e1p, *e2p;
    cudaGetSymbolAddress((void**)&obsp, g_obsp);
    cudaGetSymbolAddress((void**)&w1p,  g_w1p);
    cudaGetSymbolAddress((void**)&w2p,  g_w2p);
    cudaGetSymbolAddress((void**)&wihp, g_wihp);
    cudaGetSymbolAddress((void**)&e1p,  g_enc1p);
    cudaGetSymbolAddress((void**)&e2p,  g_enc2p);
    uint4* whhF; cudaGetSymbolAddress((void**)&whhF, g_whhF);
    float* xg; cudaGetSymbolAddress((void**)&xg, g_xg);

    const int lstm_smem = (32*260*2 + 2048 + 2048) * 4;
    cudaFuncSetAttribute(lstm_kernel, cudaFuncAttributeMaxDynamicSharedMemorySize, lstm_smem);

    conv_init<<<2048, 256>>>(obs, W1, W2, W_ih, W_hh, hxs);
    gemm_mma<1,1><<<dim3(ENC/128, MM/128), 256>>>(obsp, w1p, b1, nullptr, e1p, OBS, ENC);
    gemm_mma<1,1><<<dim3(ENC/128, MM/128), 256>>>(e1p, w2p, b2, nullptr, e2p, ENC, ENC);
    gemm_mma<0,0><<<dim3(G4/128, MM/128), 256>>>(e2p, wihp, b_ih, b_hh, xg, ENC, G4);

    lstm_kernel<<<128, 256, lstm_smem>>>(whhF, cxs, dout);
    head_kernel<<<MM/16, 256>>>(Wa, ba, Wc, bc, dout);
    loss_partial<<<LOSS_BLOCKS, 256>>>();
    loss_final<<<1, 256>>>(dout);
}